// round 7
// baseline (speedup 1.0000x reference)
#include <cuda_runtime.h>
#include <cstdint>

// ---------------------------------------------------------------------------
// TraFixV5: GRU (B*J=5120 seqs, T=128, D=64, H=128) -> GAT(5 nodes) -> MLP ->
// actor heads + critic.
// Round 6 fix: __syncthreads() before K2's cross-group write-out (round 6
// read other barrier-groups' h rows without a full-block sync -> 4.9e-2 err).
//   K1: 640 thr = 128 cols x 5 rgroups, 3 cols x 8 rows per thread.
//   K2: 512 thr = 4 groups x 128, 9 rows per thread, R_CTA=36 over 148 CTAs.
// ---------------------------------------------------------------------------

typedef unsigned long long ull;

__device__ __forceinline__ ull ffma2(ull a, ull b, ull c) {
    ull d; asm("fma.rn.f32x2 %0, %1, %2, %3;" : "=l"(d) : "l"(a), "l"(b), "l"(c));
    return d;
}
__device__ __forceinline__ float2 up2(ull v) {
    float2 r; asm("mov.b64 {%0, %1}, %2;" : "=f"(r.x), "=f"(r.y) : "l"(v)); return r;
}

#define BATCH 1024
#define TT    128
#define JJ    5
#define DD    64
#define HH    128
#define G3    384
#define BJ    5120    // BATCH*JJ
#define PAD_ROWS 208  // slack: 148 CTAs x 36 rows = 5328

// scratch (static __device__ arrays: the allocation-guard-safe path)
__device__ float g_GI[((size_t)BJ * TT + PAD_ROWS) * G3];  // [t][row][c]
__device__ float g_H[(BJ + PAD_ROWS) * HH];                // final GRU hidden

// ===========================================================================
// K1: gi = x @ W_ih^T + b_ih.  grid (128 row-tiles of 40, 8 t-chunks of 16),
// 640 threads = 128 col-lanes x 5 row-groups. Thread: cols {cg,cg+128,cg+256}
// x rows {r0..r0+7}. k(=d)-packed f32x2, horizontal add at store.
// ===========================================================================
#define K1_THREADS 640
#define K1_ROWS    40
#define DP 68   // smem stride (floats): 68 mod 32 = 4 -> conflict-free LDS.128
#define K1_SMEM ((G3 * DP + K1_ROWS * DP + G3) * 4)

__global__ void __launch_bounds__(K1_THREADS, 1)
k1_gi(const float* __restrict__ obs, const float* __restrict__ W_ih,
      const float* __restrict__ b_ih)
{
    extern __shared__ float sm[];
    float* Ws = sm;                    // [c][d] stride DP
    float* xs = sm + G3 * DP;          // [r][d] stride DP, 40 rows
    float* bs = xs + K1_ROWS * DP;     // bias [384]

    const int tid = threadIdx.x;
    const int cg  = tid & 127;         // cols cg, cg+128, cg+256
    const int rg  = tid >> 7;          // 0..4 (uniform within a warp)
    const int r0  = rg * 8;

    for (int idx = tid; idx < G3 * DD; idx += K1_THREADS) {
        int c = idx >> 6, d = idx & 63;
        Ws[c * DP + d] = W_ih[idx];
    }
    for (int idx = tid; idx < G3; idx += K1_THREADS) bs[idx] = b_ih[idx];
    __syncthreads();

    const int rowbase = blockIdx.x * K1_ROWS;
    const int tbase   = blockIdx.y * 16;

    for (int tt = 0; tt < 16; ++tt) {
        const int t = tbase + tt;
        // stage x[40 rows][64 d]
        for (int idx = tid; idx < K1_ROWS * 64; idx += K1_THREADS) {
            int r = idx >> 6, d = idx & 63;
            int row = rowbase + r;
            int b = row / 5, j = row - b * 5;
            xs[r * DP + d] = obs[(((size_t)b * TT + t) * JJ + j) * DD + d];
        }
        __syncthreads();

        ull acc[3][8];
#pragma unroll
        for (int cc = 0; cc < 3; ++cc)
#pragma unroll
            for (int r = 0; r < 8; ++r) acc[cc][r] = 0ull;

#pragma unroll 2
        for (int d = 0; d < 64; d += 4) {
            ull wlo[3], whi[3];
#pragma unroll
            for (int cc = 0; cc < 3; ++cc) {
                float4 wv = *(const float4*)(Ws + (cg + 128 * cc) * DP + d);
                wlo[cc] = *(const ull*)&wv;
                whi[cc] = *((const ull*)&wv + 1);
            }
#pragma unroll
            for (int r = 0; r < 8; ++r) {
                float4 xv = *(const float4*)(xs + (r0 + r) * DP + d);  // broadcast
                ull xlo = *(const ull*)&xv, xhi = *((const ull*)&xv + 1);
#pragma unroll
                for (int cc = 0; cc < 3; ++cc) {
                    acc[cc][r] = ffma2(xlo, wlo[cc], acc[cc][r]);
                    acc[cc][r] = ffma2(xhi, whi[cc], acc[cc][r]);
                }
            }
        }

        float* gout = g_GI + ((size_t)t * BJ + rowbase + r0) * G3;
#pragma unroll
        for (int cc = 0; cc < 3; ++cc) {
            int c = cg + 128 * cc;
            float bv = bs[c];
#pragma unroll
            for (int r = 0; r < 8; ++r) {
                float2 v = up2(acc[cc][r]);
                gout[(size_t)r * G3 + c] = v.x + v.y + bv;   // lanes coalesced
            }
        }
        __syncthreads();
    }
}

// ===========================================================================
// K2: persistent GRU. 148 CTAs x 36 rows (5328 >= 5120, padded tail).
// 512 threads = 4 groups of 128: thread (i,g) owns gate index i for the 9
// rows of group g. Named barriers per group (h rows are group-exclusive
// during the recurrence); full __syncthreads() before the cross-group
// write-out.
// ===========================================================================
#define K2_THREADS 512
#define K2_CTAS    148
#define R_CTA      36
#define RPT        9    // rows per thread
#define WCS        132  // 132 mod 32 = 4 -> conflict-free strided LDS.128
#define K2_SMEM    ((G3 * WCS + R_CTA * HH) * 4)

__global__ void __launch_bounds__(K2_THREADS, 1)
k2_gru(const float* __restrict__ W_hh, const float* __restrict__ b_hh)
{
    extern __shared__ float sm[];
    float* Wc = sm;             // [384][132]
    float* hs = sm + G3 * WCS;  // [36][128]

    const int tid = threadIdx.x;
    const int i   = tid & 127;
    const int g   = tid >> 7;   // 0..3
    const int rowbase = blockIdx.x * R_CTA;
    const int lr0 = g * RPT;    // local row base

    for (int idx = tid; idx < G3 * HH; idx += K2_THREADS) {
        int c = idx >> 7, k = idx & 127;
        Wc[c * WCS + k] = W_hh[idx];
    }
    for (int idx = tid; idx < R_CTA * HH; idx += K2_THREADS) hs[idx] = 0.f;
    __syncthreads();

    const float br = b_hh[i], bz = b_hh[HH + i], bn = b_hh[2 * HH + i];
    const float* Wr = Wc + i * WCS;
    const float* Wz = Wc + (HH + i) * WCS;
    const float* Wn = Wc + (2 * HH + i) * WCS;
    const float* hb = hs + lr0 * HH;

    for (int t = 0; t < TT; ++t) {
        // hoist gi loads: latency hidden under the ~14k-cycle k-loop
        const float* gi = g_GI + ((size_t)t * BJ + rowbase + lr0) * G3;
        float gr[RPT], gz[RPT], gn[RPT];
#pragma unroll
        for (int p = 0; p < RPT; ++p) {
            const float* q = gi + (size_t)p * G3;
            gr[p] = __ldg(q + i); gz[p] = __ldg(q + HH + i); gn[p] = __ldg(q + 2 * HH + i);
        }

        ull ar[RPT], az[RPT], an[RPT];
#pragma unroll
        for (int p = 0; p < RPT; ++p) { ar[p] = 0ull; az[p] = 0ull; an[p] = 0ull; }

#pragma unroll 2
        for (int k = 0; k < HH; k += 4) {
            float4 w4r = *(const float4*)(Wr + k);
            float4 w4z = *(const float4*)(Wz + k);
            float4 w4n = *(const float4*)(Wn + k);
            ull wrlo = *(const ull*)&w4r, wrhi = *((const ull*)&w4r + 1);
            ull wzlo = *(const ull*)&w4z, wzhi = *((const ull*)&w4z + 1);
            ull wnlo = *(const ull*)&w4n, wnhi = *((const ull*)&w4n + 1);
#pragma unroll
            for (int p = 0; p < RPT; ++p) {
                float4 h4 = *(const float4*)(hb + p * HH + k);   // broadcast
                ull hlo = *(const ull*)&h4, hhi = *((const ull*)&h4 + 1);
                ar[p] = ffma2(hlo, wrlo, ar[p]); ar[p] = ffma2(hhi, wrhi, ar[p]);
                az[p] = ffma2(hlo, wzlo, az[p]); az[p] = ffma2(hhi, wzhi, az[p]);
                an[p] = ffma2(hlo, wnlo, an[p]); an[p] = ffma2(hhi, wnhi, an[p]);
            }
        }

        float hnew[RPT];
#pragma unroll
        for (int p = 0; p < RPT; ++p) {
            float2 vr = up2(ar[p]), vz = up2(az[p]), vn = up2(an[p]);
            float ghr = vr.x + vr.y + br;
            float ghz = vz.x + vz.y + bz;
            float ghn = vn.x + vn.y + bn;
            float hold = hs[(lr0 + p) * HH + i];
            float r = 1.f / (1.f + __expf(-(gr[p] + ghr)));
            float z = 1.f / (1.f + __expf(-(gz[p] + ghz)));
            float n = tanhf(gn[p] + r * ghn);
            hnew[p] = (1.f - z) * n + z * hold;
        }
        asm volatile("bar.sync %0, %1;" :: "r"(g + 1), "r"(128) : "memory");
#pragma unroll
        for (int p = 0; p < RPT; ++p) hs[(lr0 + p) * HH + i] = hnew[p];
        asm volatile("bar.sync %0, %1;" :: "r"(g + 1), "r"(128) : "memory");
    }

    // FULL block sync: the write-out below reads rows owned by other named-
    // barrier groups (this was the round-6 correctness bug).
    __syncthreads();

    // final h -> gmem (rows >= 5120 land in the padded tail of g_H)
    for (int idx = tid; idx < R_CTA * HH; idx += K2_THREADS) {
        int r = idx >> 7, k = idx & 127;
        g_H[(rowbase + r) * HH + k] = hs[r * HH + k];
    }
}

// ===========================================================================
// K3: GAT + trunk MLP + actor/critic.  256 blocks x 256 threads, 4 batches
// per block; all weights staged in smem once per block.  (unchanged)
// ===========================================================================
#define K3_THREADS 256
#define K3_SMEM ((16384 + 16384 + 8192 + 640 * 4 + 320 + 20 + 20 + 100 + 8 + 32) * 4)

__global__ void __launch_bounds__(K3_THREADS, 1)
k3_head(const int* __restrict__ edge,
        const float* __restrict__ gat_W, const float* __restrict__ att_src,
        const float* __restrict__ att_dst, const float* __restrict__ gat_b,
        const float* __restrict__ W1, const float* __restrict__ b1,
        const float* __restrict__ W2, const float* __restrict__ b2,
        const float* __restrict__ actW, const float* __restrict__ actb,
        const float* __restrict__ crW, const float* __restrict__ crb,
        float* __restrict__ out)
{
    extern __shared__ float sm[];
    float* gatW_s = sm;              // 16384  [k][o]
    float* W1_s   = gatW_s + 16384;  // 16384  [o][m]
    float* W2_s   = W1_s + 16384;    // 8192   [m][u]
    float* h_s    = W2_s + 8192;     // 640
    float* xp_s   = h_s + 640;       // 640
    float* g_s    = xp_s + 640;      // 640
    float* t1_s   = g_s + 640;       // 640
    float* t2_s   = t1_s + 640;      // 320
    float* as_s   = t2_s + 320;      // 20
    float* ad_s   = as_s + 20;       // 20
    float* al_s   = ad_s + 20;       // 100  alpha [i][j][head]
    float* red_s  = al_s + 100;      // 8
    int*   adj_s  = (int*)(red_s + 8);

    const int tid = threadIdx.x;

    for (int idx = tid; idx < 16384; idx += K3_THREADS) gatW_s[idx] = gat_W[idx];
    for (int idx = tid; idx < 16384; idx += K3_THREADS) W1_s[idx] = W1[idx];
    for (int idx = tid; idx < 8192;  idx += K3_THREADS) W2_s[idx] = W2[idx];
    if (tid < 25) adj_s[tid] = (tid / 5 == tid % 5) ? 1 : 0;  // self-loops
    __syncthreads();
    if (tid < 8) adj_s[edge[8 + tid] * 5 + edge[tid]] = 1;     // adj[dst][src]
    __syncthreads();

    for (int bb = 0; bb < 4; ++bb) {
        const int batch = blockIdx.x * 4 + bb;

        for (int idx = tid; idx < 640; idx += K3_THREADS)
            h_s[idx] = g_H[batch * 5 * HH + idx];
        __syncthreads();

        // xp = h @ gat_W
        for (int idx = tid; idx < 640; idx += K3_THREADS) {
            int j = idx >> 7, o = idx & 127;
            float a = 0.f;
#pragma unroll 8
            for (int k = 0; k < 128; ++k) a += h_s[j * 128 + k] * gatW_s[k * 128 + o];
            xp_s[idx] = a;
        }
        __syncthreads();

        // attention scores per (j, head)
        if (tid < 20) {
            int j = tid >> 2, h = tid & 3;
            float s1 = 0.f, s2 = 0.f;
            for (int d = 0; d < 32; ++d) {
                float v = xp_s[j * 128 + h * 32 + d];
                s1 += v * att_src[h * 32 + d];
                s2 += v * att_dst[h * 32 + d];
            }
            as_s[tid] = s1; ad_s[tid] = s2;
        }
        __syncthreads();

        // masked leaky-relu softmax over src j per (dst i, head)
        if (tid < 20) {
            int ii = tid >> 2, h = tid & 3;
            float ev[5]; float m = -1e30f;
#pragma unroll
            for (int j = 0; j < 5; ++j) {
                float e = as_s[j * 4 + h] + ad_s[ii * 4 + h];
                e = e > 0.f ? e : 0.2f * e;
                if (!adj_s[ii * 5 + j]) e = -1e30f;
                ev[j] = e; m = fmaxf(m, e);
            }
            float s = 0.f;
#pragma unroll
            for (int j = 0; j < 5; ++j) {
                ev[j] = adj_s[ii * 5 + j] ? __expf(ev[j] - m) : 0.f;
                s += ev[j];
            }
            float inv = 1.f / s;
#pragma unroll
            for (int j = 0; j < 5; ++j) al_s[(ii * 5 + j) * 4 + h] = ev[j] * inv;
        }
        __syncthreads();

        // aggregate: g[i][o] = sum_j alpha[i][j][o/32] * xp[j][o] + gat_b
        for (int idx = tid; idx < 640; idx += K3_THREADS) {
            int ii = idx >> 7, o = idx & 127;
            int h = o >> 5;
            float a = gat_b[o];
#pragma unroll
            for (int j = 0; j < 5; ++j) a += al_s[(ii * 5 + j) * 4 + h] * xp_s[j * 128 + o];
            g_s[idx] = a;
        }
        __syncthreads();

        // t1 = relu(g @ W1 + b1)
        for (int idx = tid; idx < 640; idx += K3_THREADS) {
            int ii = idx >> 7, m2 = idx & 127;
            float a = b1[m2];
#pragma unroll 8
            for (int o = 0; o < 128; ++o) a += g_s[ii * 128 + o] * W1_s[o * 128 + m2];
            t1_s[idx] = fmaxf(a, 0.f);
        }
        __syncthreads();

        // t2 = relu(t1 @ W2 + b2)
        for (int idx = tid; idx < 320; idx += K3_THREADS) {
            int ii = idx >> 6, u = idx & 63;
            float a = b2[u];
#pragma unroll 8
            for (int m2 = 0; m2 < 128; ++m2) a += t1_s[ii * 128 + m2] * W2_s[m2 * 64 + u];
            t2_s[idx] = fmaxf(a, 0.f);
        }
        __syncthreads();

        // per-junction actor logits
        if (tid < 20) {
            int j = tid >> 2, p = tid & 3;
            float a = actb[j * 4 + p];
            for (int u = 0; u < 64; ++u) a += t2_s[j * 64 + u] * actW[(j * 64 + u) * 4 + p];
            out[batch * 20 + j * 4 + p] = a;
        }

        // critic on junction mean
        float v = 0.f;
        if (tid < 64) {
            float s = t2_s[tid] + t2_s[64 + tid] + t2_s[128 + tid] +
                      t2_s[192 + tid] + t2_s[256 + tid];
            v = s * 0.2f * crW[tid];
        }
        v += __shfl_down_sync(0xffffffffu, v, 16);
        v += __shfl_down_sync(0xffffffffu, v, 8);
        v += __shfl_down_sync(0xffffffffu, v, 4);
        v += __shfl_down_sync(0xffffffffu, v, 2);
        v += __shfl_down_sync(0xffffffffu, v, 1);
        if (tid < 64 && (tid & 31) == 0) red_s[tid >> 5] = v;
        __syncthreads();
        if (tid == 0) out[BATCH * JJ * 4 + batch] = red_s[0] + red_s[1] + crb[0];
        __syncthreads();   // buffers reused by next batch
    }
}

// ===========================================================================
extern "C" void kernel_launch(void* const* d_in, const int* in_sizes, int n_in,
                              void* d_out, int out_size)
{
    const float* obs     = (const float*)d_in[0];
    const int*   edge    = (const int*)  d_in[1];
    const float* W_ih    = (const float*)d_in[2];
    const float* W_hh    = (const float*)d_in[3];
    const float* b_ih    = (const float*)d_in[4];
    const float* b_hh    = (const float*)d_in[5];
    const float* gat_W   = (const float*)d_in[6];
    const float* att_src = (const float*)d_in[7];
    const float* att_dst = (const float*)d_in[8];
    const float* gat_b   = (const float*)d_in[9];
    const float* W1      = (const float*)d_in[10];
    const float* b1      = (const float*)d_in[11];
    const float* W2      = (const float*)d_in[12];
    const float* b2      = (const float*)d_in[13];
    const float* actW    = (const float*)d_in[14];
    const float* actb    = (const float*)d_in[15];
    const float* crW     = (const float*)d_in[16];
    const float* crb     = (const float*)d_in[17];
    float* out = (float*)d_out;

    cudaFuncSetAttribute(k1_gi,   cudaFuncAttributeMaxDynamicSharedMemorySize, K1_SMEM);
    cudaFuncSetAttribute(k2_gru,  cudaFuncAttributeMaxDynamicSharedMemorySize, K2_SMEM);
    cudaFuncSetAttribute(k3_head, cudaFuncAttributeMaxDynamicSharedMemorySize, K3_SMEM);

    k1_gi<<<dim3(128, 8), K1_THREADS, K1_SMEM>>>(obs, W_ih, b_ih);
    k2_gru<<<K2_CTAS, K2_THREADS, K2_SMEM>>>(W_hh, b_hh);
    k3_head<<<256, K3_THREADS, K3_SMEM>>>(edge, gat_W, att_src, att_dst, gat_b,
                                          W1, b1, W2, b2, actW, actb, crW, crb, out);
}

// round 11
// speedup vs baseline: 1.2502x; 1.2502x over previous
#include <cuda_runtime.h>
#include <cuda_bf16.h>
#include <cstdint>

// ---------------------------------------------------------------------------
// TraFixV5: GRU (B*J=5120 seqs, T=128, D=64, H=128) -> GAT(5 nodes) -> MLP ->
// actor heads + critic.
// Round 9: tcgen05 is NOT compilable under this harness (ptxas lowers via
// compute_103 without the 'a' feature set). K1 now uses warp-level HMMA
// (mma.sync m16n8k16 bf16, base ISA) with hi/lo split precision; W fragments
// register-resident. K2/K3 unchanged from the passing round-7 kernel.
// ---------------------------------------------------------------------------

typedef unsigned long long ull;

__device__ __forceinline__ ull ffma2(ull a, ull b, ull c) {
    ull d; asm("fma.rn.f32x2 %0, %1, %2, %3;" : "=l"(d) : "l"(a), "l"(b), "l"(c));
    return d;
}
__device__ __forceinline__ float2 up2(ull v) {
    float2 r; asm("mov.b64 {%0, %1}, %2;" : "=f"(r.x), "=f"(r.y) : "l"(v)); return r;
}

#define BATCH 1024
#define TT    128
#define JJ    5
#define DD    64
#define HH    128
#define G3    384
#define BJ    5120
#define PAD_ROWS 208  // slack: 148 CTAs x 36 rows = 5328

__device__ float g_GI[((size_t)BJ * TT + PAD_ROWS) * G3];  // [t][row][c]
__device__ float g_H[(BJ + PAD_ROWS) * HH];

// ===========================================================================
// HMMA helpers
// ===========================================================================
__device__ __forceinline__ uint32_t smem_u32(const void* p) {
    uint32_t a;
    asm("{ .reg .u64 t; cvta.to.shared.u64 t, %1; cvt.u32.u64 %0, t; }"
        : "=r"(a) : "l"(p));
    return a;
}
__device__ __forceinline__ void ldsm4(uint32_t& r0, uint32_t& r1,
                                      uint32_t& r2, uint32_t& r3, uint32_t addr) {
    asm volatile("ldmatrix.sync.aligned.m8n8.x4.shared.b16 {%0,%1,%2,%3}, [%4];"
                 : "=r"(r0), "=r"(r1), "=r"(r2), "=r"(r3) : "r"(addr));
}
__device__ __forceinline__ void mma16816(float* d, uint32_t a0, uint32_t a1,
                                         uint32_t a2, uint32_t a3,
                                         uint32_t b0, uint32_t b1) {
    asm volatile(
        "mma.sync.aligned.m16n8k16.row.col.f32.bf16.bf16.f32 "
        "{%0,%1,%2,%3}, {%4,%5,%6,%7}, {%8,%9}, {%0,%1,%2,%3};"
        : "+f"(d[0]), "+f"(d[1]), "+f"(d[2]), "+f"(d[3])
        : "r"(a0), "r"(a1), "r"(a2), "r"(a3), "r"(b0), "r"(b1));
}
// split f32 -> (hi bf16, lo bf16=residual), packed pairs (low 16 = elem k)
__device__ __forceinline__ void split2(float x, float y, uint32_t& hi, uint32_t& lo) {
    __nv_bfloat16 hx = __float2bfloat16(x), hy = __float2bfloat16(y);
    float rx = x - __bfloat162float(hx), ry = y - __bfloat162float(hy);
    __nv_bfloat16 lx = __float2bfloat16(rx), ly = __float2bfloat16(ry);
    hi = ((uint32_t)__bfloat16_as_ushort(hy) << 16) | __bfloat16_as_ushort(hx);
    lo = ((uint32_t)__bfloat16_as_ushort(ly) << 16) | __bfloat16_as_ushort(lx);
}

// ===========================================================================
// K1 (HMMA): gi = x @ W_ih^T + b_ih.
// 5120 tiles of [M=128, K=64]; N=384 split as 8 warps x 48 cols.
// B (W_ih) fragments register-resident (hi/lo); A staged in smem as bf16
// hi/lo with (chunk ^ row&7) 16B swizzle for conflict-free ldmatrix.
// Terms: Ahi*Bhi + Alo*Bhi + Ahi*Blo (f32 accum).
// ===========================================================================
#define K1_GRID    640
#define K1_THREADS 256
#define A_BYTES    (128 * 128)     // 128 rows x 64 bf16 (128 B/row)
#define K1M_SMEM   (2 * A_BYTES)   // AHI + ALO = 32 KB

__global__ void __launch_bounds__(K1_THREADS, 1)
k1_gi_mma(const float* __restrict__ obs, const float* __restrict__ W_ih,
          const float* __restrict__ b_ih)
{
    extern __shared__ char smc[];
    char* AHI = smc;
    char* ALO = smc + A_BYTES;
    const uint32_t ahi_b = smem_u32(AHI);
    const uint32_t alo_b = smem_u32(ALO);

    const int tid = threadIdx.x;
    const int wid = tid >> 5;
    const int lid = tid & 31;
    const int wn0 = wid * 48;          // this warp's N base (48 cols)
    const int lg  = lid >> 2;          // lane group 0..7
    const int lq  = lid & 3;           // lane quad  0..3

    // ---- B fragments (register-resident): Bhi/Blo[nt][ks][2] ----
    uint32_t Bhi[6][4][2], Blo[6][4][2];
    float    bias0[6], bias1[6];
#pragma unroll
    for (int nt = 0; nt < 6; ++nt) {
        const int n = wn0 + nt * 8 + lg;
#pragma unroll
        for (int ks = 0; ks < 4; ++ks) {
            const int k = ks * 16 + 2 * lq;
            float2 v0 = *(const float2*)(W_ih + n * DD + k);      // k, k+1
            float2 v1 = *(const float2*)(W_ih + n * DD + k + 8);  // k+8, k+9
            split2(v0.x, v0.y, Bhi[nt][ks][0], Blo[nt][ks][0]);
            split2(v1.x, v1.y, Bhi[nt][ks][1], Blo[nt][ks][1]);
        }
        const int c0 = wn0 + nt * 8 + 2 * lq;   // D fragment cols for this lane
        bias0[nt] = b_ih[c0];
        bias1[nt] = b_ih[c0 + 1];
    }

    for (int tile = blockIdx.x; tile < 5120; tile += K1_GRID) {
        const int t  = tile / 40;
        const int rb = (tile - t * 40) * 128;

        // ---- stage A tile [128 rows][64 d] -> bf16 hi/lo, swizzled ----
        for (int idx = tid; idx < 128 * 32; idx += K1_THREADS) {
            const int r  = idx >> 5;
            const int dp = idx & 31;               // d-pair index (2 f32)
            const int row = rb + r;
            const int b = row / 5, j = row - b * 5;
            float2 v = *(const float2*)(obs + (((size_t)b * TT + t) * JJ + j) * DD + 2 * dp);
            uint32_t hi, lo;
            split2(v.x, v.y, hi, lo);
            const uint32_t off = r * 128 + (((dp >> 2) ^ (r & 7)) << 4) + ((dp & 3) << 2);
            *(uint32_t*)(AHI + off) = hi;
            *(uint32_t*)(ALO + off) = lo;
        }
        __syncthreads();

        // ---- compute: 8 m-tiles x (4 k-steps x 6 n-tiles x 3 terms) ----
        const int row_l = lid & 15;                 // ldmatrix row within m-tile
        const int kc    = lid >> 4;                 // 0/1 -> k-half chunk
#pragma unroll 1
        for (int mt = 0; mt < 8; ++mt) {
            float acc[6][4];
#pragma unroll
            for (int nt = 0; nt < 6; ++nt)
#pragma unroll
                for (int q = 0; q < 4; ++q) acc[nt][q] = 0.f;

            const int arow = mt * 16 + row_l;
#pragma unroll
            for (int ks = 0; ks < 4; ++ks) {
                const int chunk = 2 * ks + kc;
                const uint32_t aoff = arow * 128 + ((chunk ^ (arow & 7)) << 4);
                uint32_t ah0, ah1, ah2, ah3, al0, al1, al2, al3;
                ldsm4(ah0, ah1, ah2, ah3, ahi_b + aoff);
                ldsm4(al0, al1, al2, al3, alo_b + aoff);
#pragma unroll
                for (int nt = 0; nt < 6; ++nt) {
                    mma16816(acc[nt], ah0, ah1, ah2, ah3,
                             Bhi[nt][ks][0], Bhi[nt][ks][1]);
                    mma16816(acc[nt], al0, al1, al2, al3,
                             Bhi[nt][ks][0], Bhi[nt][ks][1]);
                    mma16816(acc[nt], ah0, ah1, ah2, ah3,
                             Blo[nt][ks][0], Blo[nt][ks][1]);
                }
            }

            // ---- epilogue: D fragment -> g_GI (+bias) ----
            const int r0 = rb + mt * 16 + lg;       // rows lg, lg+8
            float* o0 = g_GI + ((size_t)t * BJ + r0) * G3;
            float* o1 = o0 + (size_t)8 * G3;
#pragma unroll
            for (int nt = 0; nt < 6; ++nt) {
                const int c = wn0 + nt * 8 + 2 * lq;
                *(float2*)(o0 + c) = make_float2(acc[nt][0] + bias0[nt],
                                                 acc[nt][1] + bias1[nt]);
                *(float2*)(o1 + c) = make_float2(acc[nt][2] + bias0[nt],
                                                 acc[nt][3] + bias1[nt]);
            }
        }
        __syncthreads();   // A smem reused by next tile's staging
    }
}

// ===========================================================================
// K2: persistent GRU (SIMT f32x2) — unchanged from passing round 7.
// ===========================================================================
#define K2_THREADS 512
#define K2_CTAS    148
#define R_CTA      36
#define RPT        9
#define WCS        132
#define K2_SMEM    ((G3 * WCS + R_CTA * HH) * 4)

__global__ void __launch_bounds__(K2_THREADS, 1)
k2_gru(const float* __restrict__ W_hh, const float* __restrict__ b_hh)
{
    extern __shared__ float sm[];
    float* Wc = sm;             // [384][132]
    float* hs = sm + G3 * WCS;  // [36][128]

    const int tid = threadIdx.x;
    const int i   = tid & 127;
    const int g   = tid >> 7;
    const int rowbase = blockIdx.x * R_CTA;
    const int lr0 = g * RPT;

    for (int idx = tid; idx < G3 * HH; idx += K2_THREADS) {
        int c = idx >> 7, k = idx & 127;
        Wc[c * WCS + k] = W_hh[idx];
    }
    for (int idx = tid; idx < R_CTA * HH; idx += K2_THREADS) hs[idx] = 0.f;
    __syncthreads();

    const float br = b_hh[i], bz = b_hh[HH + i], bn = b_hh[2 * HH + i];
    const float* Wr = Wc + i * WCS;
    const float* Wz = Wc + (HH + i) * WCS;
    const float* Wn = Wc + (2 * HH + i) * WCS;
    const float* hb = hs + lr0 * HH;

    for (int t = 0; t < TT; ++t) {
        const float* gi = g_GI + ((size_t)t * BJ + rowbase + lr0) * G3;
        float gr[RPT], gz[RPT], gn[RPT];
#pragma unroll
        for (int p = 0; p < RPT; ++p) {
            const float* q = gi + (size_t)p * G3;
            gr[p] = __ldg(q + i); gz[p] = __ldg(q + HH + i); gn[p] = __ldg(q + 2 * HH + i);
        }

        ull ar[RPT], az[RPT], an[RPT];
#pragma unroll
        for (int p = 0; p < RPT; ++p) { ar[p] = 0ull; az[p] = 0ull; an[p] = 0ull; }

#pragma unroll 2
        for (int k = 0; k < HH; k += 4) {
            float4 w4r = *(const float4*)(Wr + k);
            float4 w4z = *(const float4*)(Wz + k);
            float4 w4n = *(const float4*)(Wn + k);
            ull wrlo = *(const ull*)&w4r, wrhi = *((const ull*)&w4r + 1);
            ull wzlo = *(const ull*)&w4z, wzhi = *((const ull*)&w4z + 1);
            ull wnlo = *(const ull*)&w4n, wnhi = *((const ull*)&w4n + 1);
#pragma unroll
            for (int p = 0; p < RPT; ++p) {
                float4 h4 = *(const float4*)(hb + p * HH + k);
                ull hlo = *(const ull*)&h4, hhi = *((const ull*)&h4 + 1);
                ar[p] = ffma2(hlo, wrlo, ar[p]); ar[p] = ffma2(hhi, wrhi, ar[p]);
                az[p] = ffma2(hlo, wzlo, az[p]); az[p] = ffma2(hhi, wzhi, az[p]);
                an[p] = ffma2(hlo, wnlo, an[p]); an[p] = ffma2(hhi, wnhi, an[p]);
            }
        }

        float hnew[RPT];
#pragma unroll
        for (int p = 0; p < RPT; ++p) {
            float2 vr = up2(ar[p]), vz = up2(az[p]), vn = up2(an[p]);
            float ghr = vr.x + vr.y + br;
            float ghz = vz.x + vz.y + bz;
            float ghn = vn.x + vn.y + bn;
            float hold = hs[(lr0 + p) * HH + i];
            float r = 1.f / (1.f + __expf(-(gr[p] + ghr)));
            float z = 1.f / (1.f + __expf(-(gz[p] + ghz)));
            float n = tanhf(gn[p] + r * ghn);
            hnew[p] = (1.f - z) * n + z * hold;
        }
        asm volatile("bar.sync %0, %1;" :: "r"(g + 1), "r"(128) : "memory");
#pragma unroll
        for (int p = 0; p < RPT; ++p) hs[(lr0 + p) * HH + i] = hnew[p];
        asm volatile("bar.sync %0, %1;" :: "r"(g + 1), "r"(128) : "memory");
    }

    __syncthreads();   // cross-group write-out below
    for (int idx = tid; idx < R_CTA * HH; idx += K2_THREADS) {
        int r = idx >> 7, k = idx & 127;
        g_H[(rowbase + r) * HH + k] = hs[r * HH + k];
    }
}

// ===========================================================================
// K3: GAT + trunk MLP + actor/critic. (unchanged, passing)
// ===========================================================================
#define K3_THREADS 256
#define K3_SMEM ((16384 + 16384 + 8192 + 640 * 4 + 320 + 20 + 20 + 100 + 8 + 32) * 4)

__global__ void __launch_bounds__(K3_THREADS, 1)
k3_head(const int* __restrict__ edge,
        const float* __restrict__ gat_W, const float* __restrict__ att_src,
        const float* __restrict__ att_dst, const float* __restrict__ gat_b,
        const float* __restrict__ W1, const float* __restrict__ b1,
        const float* __restrict__ W2, const float* __restrict__ b2,
        const float* __restrict__ actW, const float* __restrict__ actb,
        const float* __restrict__ crW, const float* __restrict__ crb,
        float* __restrict__ out)
{
    extern __shared__ float sm[];
    float* gatW_s = sm;
    float* W1_s   = gatW_s + 16384;
    float* W2_s   = W1_s + 16384;
    float* h_s    = W2_s + 8192;
    float* xp_s   = h_s + 640;
    float* g_s    = xp_s + 640;
    float* t1_s   = g_s + 640;
    float* t2_s   = t1_s + 640;
    float* as_s   = t2_s + 320;
    float* ad_s   = as_s + 20;
    float* al_s   = ad_s + 20;
    float* red_s  = al_s + 100;
    int*   adj_s  = (int*)(red_s + 8);

    const int tid = threadIdx.x;

    for (int idx = tid; idx < 16384; idx += K3_THREADS) gatW_s[idx] = gat_W[idx];
    for (int idx = tid; idx < 16384; idx += K3_THREADS) W1_s[idx] = W1[idx];
    for (int idx = tid; idx < 8192;  idx += K3_THREADS) W2_s[idx] = W2[idx];
    if (tid < 25) adj_s[tid] = (tid / 5 == tid % 5) ? 1 : 0;
    __syncthreads();
    if (tid < 8) adj_s[edge[8 + tid] * 5 + edge[tid]] = 1;
    __syncthreads();

    for (int bb = 0; bb < 4; ++bb) {
        const int batch = blockIdx.x * 4 + bb;

        for (int idx = tid; idx < 640; idx += K3_THREADS)
            h_s[idx] = g_H[batch * 5 * HH + idx];
        __syncthreads();

        for (int idx = tid; idx < 640; idx += K3_THREADS) {
            int j = idx >> 7, o = idx & 127;
            float a = 0.f;
#pragma unroll 8
            for (int k = 0; k < 128; ++k) a += h_s[j * 128 + k] * gatW_s[k * 128 + o];
            xp_s[idx] = a;
        }
        __syncthreads();

        if (tid < 20) {
            int j = tid >> 2, h = tid & 3;
            float s1 = 0.f, s2 = 0.f;
            for (int d = 0; d < 32; ++d) {
                float v = xp_s[j * 128 + h * 32 + d];
                s1 += v * att_src[h * 32 + d];
                s2 += v * att_dst[h * 32 + d];
            }
            as_s[tid] = s1; ad_s[tid] = s2;
        }
        __syncthreads();

        if (tid < 20) {
            int ii = tid >> 2, h = tid & 3;
            float ev[5]; float m = -1e30f;
#pragma unroll
            for (int j = 0; j < 5; ++j) {
                float e = as_s[j * 4 + h] + ad_s[ii * 4 + h];
                e = e > 0.f ? e : 0.2f * e;
                if (!adj_s[ii * 5 + j]) e = -1e30f;
                ev[j] = e; m = fmaxf(m, e);
            }
            float s = 0.f;
#pragma unroll
            for (int j = 0; j < 5; ++j) {
                ev[j] = adj_s[ii * 5 + j] ? __expf(ev[j] - m) : 0.f;
                s += ev[j];
            }
            float inv = 1.f / s;
#pragma unroll
            for (int j = 0; j < 5; ++j) al_s[(ii * 5 + j) * 4 + h] = ev[j] * inv;
        }
        __syncthreads();

        for (int idx = tid; idx < 640; idx += K3_THREADS) {
            int ii = idx >> 7, o = idx & 127;
            int h = o >> 5;
            float a = gat_b[o];
#pragma unroll
            for (int j = 0; j < 5; ++j) a += al_s[(ii * 5 + j) * 4 + h] * xp_s[j * 128 + o];
            g_s[idx] = a;
        }
        __syncthreads();

        for (int idx = tid; idx < 640; idx += K3_THREADS) {
            int ii = idx >> 7, m2 = idx & 127;
            float a = b1[m2];
#pragma unroll 8
            for (int o = 0; o < 128; ++o) a += g_s[ii * 128 + o] * W1_s[o * 128 + m2];
            t1_s[idx] = fmaxf(a, 0.f);
        }
        __syncthreads();

        for (int idx = tid; idx < 320; idx += K3_THREADS) {
            int ii = idx >> 6, u = idx & 63;
            float a = b2[u];
#pragma unroll 8
            for (int m2 = 0; m2 < 128; ++m2) a += t1_s[ii * 128 + m2] * W2_s[m2 * 64 + u];
            t2_s[idx] = fmaxf(a, 0.f);
        }
        __syncthreads();

        if (tid < 20) {
            int j = tid >> 2, p = tid & 3;
            float a = actb[j * 4 + p];
            for (int u = 0; u < 64; ++u) a += t2_s[j * 64 + u] * actW[(j * 64 + u) * 4 + p];
            out[batch * 20 + j * 4 + p] = a;
        }

        float v = 0.f;
        if (tid < 64) {
            float s = t2_s[tid] + t2_s[64 + tid] + t2_s[128 + tid] +
                      t2_s[192 + tid] + t2_s[256 + tid];
            v = s * 0.2f * crW[tid];
        }
        v += __shfl_down_sync(0xffffffffu, v, 16);
        v += __shfl_down_sync(0xffffffffu, v, 8);
        v += __shfl_down_sync(0xffffffffu, v, 4);
        v += __shfl_down_sync(0xffffffffu, v, 2);
        v += __shfl_down_sync(0xffffffffu, v, 1);
        if (tid < 64 && (tid & 31) == 0) red_s[tid >> 5] = v;
        __syncthreads();
        if (tid == 0) out[BATCH * JJ * 4 + batch] = red_s[0] + red_s[1] + crb[0];
        __syncthreads();
    }
}

// ===========================================================================
extern "C" void kernel_launch(void* const* d_in, const int* in_sizes, int n_in,
                              void* d_out, int out_size)
{
    const float* obs     = (const float*)d_in[0];
    const int*   edge    = (const int*)  d_in[1];
    const float* W_ih    = (const float*)d_in[2];
    const float* W_hh    = (const float*)d_in[3];
    const float* b_ih    = (const float*)d_in[4];
    const float* b_hh    = (const float*)d_in[5];
    const float* gat_W   = (const float*)d_in[6];
    const float* att_src = (const float*)d_in[7];
    const float* att_dst = (const float*)d_in[8];
    const float* gat_b   = (const float*)d_in[9];
    const float* W1      = (const float*)d_in[10];
    const float* b1      = (const float*)d_in[11];
    const float* W2      = (const float*)d_in[12];
    const float* b2      = (const float*)d_in[13];
    const float* actW    = (const float*)d_in[14];
    const float* actb    = (const float*)d_in[15];
    const float* crW     = (const float*)d_in[16];
    const float* crb     = (const float*)d_in[17];
    float* out = (float*)d_out;

    cudaFuncSetAttribute(k1_gi_mma, cudaFuncAttributeMaxDynamicSharedMemorySize, K1M_SMEM);
    cudaFuncSetAttribute(k2_gru,    cudaFuncAttributeMaxDynamicSharedMemorySize, K2_SMEM);
    cudaFuncSetAttribute(k3_head,   cudaFuncAttributeMaxDynamicSharedMemorySize, K3_SMEM);

    k1_gi_mma<<<K1_GRID, K1_THREADS, K1M_SMEM>>>(obs, W_ih, b_ih);
    k2_gru<<<K2_CTAS, K2_THREADS, K2_SMEM>>>(W_hh, b_hh);
    k3_head<<<256, K3_THREADS, K3_SMEM>>>(edge, gat_W, att_src, att_dst, gat_b,
                                          W1, b1, W2, b2, actW, actb, crW, crb, out);
}